// round 7
// baseline (speedup 1.0000x reference)
#include <cuda_runtime.h>

#define NN 50000
#define EE 600000
#define DH 128
#define DO 40
#define BN_EPS 1e-5f
#define SCAN_B 49            // ceil(NN/1024)
#define GB 391               // ceil(NN/128) gemm blocks
#define NCH 4                // pipeline chunks
#define CHB 98               // gemm blocks per chunk (last = 97)
#define CHR (CHB * 128)      // rows per chunk = 12544

// ---------------- scratch (device globals; referenced by symbol only) -------
__device__ __align__(16) float g_h[(size_t)NN * DH];
__device__ __align__(16) float g_a[(size_t)NN * DH];
__device__ __align__(16) float g_b[(size_t)NN * DH];
__device__ int   g_cnt[NN];
__device__ int   g_start[NN + 1];
__device__ int   g_cursor[NN];
__device__ int   g_srcCSR[EE];
__device__ float g_dinv[NN];
__device__ int   g_is64;
__device__ int   g_bsum[SCAN_B];

template <int ID>
__device__ __forceinline__ float* buf() {
    if (ID == 0) return (float*)g_h;
    if (ID == 1) return (float*)g_a;
    return (float*)g_b;
}

__device__ __forceinline__ int load_idx(const void* ei, int pos) {
    if (g_is64) return (int)((const long long*)ei)[pos];
    return ((const int*)ei)[pos];
}

// ---------------- zero counters + dtype detection (fused) -------------------
__global__ void k_zero(const int* __restrict__ w) {
    int i = blockIdx.x * blockDim.x + threadIdx.x;
    if (i < NN) g_cnt[i] = 0;
    if (i == 0) {
        int all0 = 1;
#pragma unroll
        for (int k = 1; k < 32; k += 2) all0 &= (w[k] == 0);
        g_is64 = all0;
    }
}

__global__ void k_count(const void* __restrict__ ei) {
    int e = blockIdx.x * blockDim.x + threadIdx.x;
    if (e < EE) {
        int t = load_idx(ei, EE + e);
        if ((unsigned)t < NN) atomicAdd(&g_cnt[t], 1);
    }
}

// ---- scan1: block-local inclusive scan over 1024-tiles ---------------------
__global__ void k_scan1() {
    __shared__ int wsum[32];
    int tid  = threadIdx.x;
    int lane = tid & 31;
    int wid  = tid >> 5;
    int i = blockIdx.x * 1024 + tid;
    int c = (i < NN) ? g_cnt[i] : 0;
    int v = c;
#pragma unroll
    for (int off = 1; off < 32; off <<= 1) {
        int n = __shfl_up_sync(0xffffffffu, v, off);
        if (lane >= off) v += n;
    }
    if (lane == 31) wsum[wid] = v;
    __syncthreads();
    if (wid == 0) {
        int s = wsum[lane];
#pragma unroll
        for (int off = 1; off < 32; off <<= 1) {
            int n = __shfl_up_sync(0xffffffffu, s, off);
            if (lane >= off) s += n;
        }
        wsum[lane] = s;
    }
    __syncthreads();
    int incl = ((wid == 0) ? 0 : wsum[wid - 1]) + v;
    if (i < NN) g_start[i] = incl;
    if (tid == 1023) g_bsum[blockIdx.x] = incl;
}

// ---- scan23: tile offset (warp-reduce of g_bsum) + finalize -----------------
__global__ void k_scan23() {
    __shared__ int s_off;
    int tid = threadIdx.x;
    int bq  = blockIdx.x >> 2;
    if (tid < 32) {
        int lane = tid;
        int v = (lane < bq) ? g_bsum[lane] : 0;
        if (lane + 32 < bq) v += g_bsum[lane + 32];
#pragma unroll
        for (int off = 16; off > 0; off >>= 1)
            v += __shfl_xor_sync(0xffffffffu, v, off);
        if (lane == 0) s_off = v;
    }
    __syncthreads();
    int boff = s_off;
    int i = blockIdx.x * blockDim.x + tid;
    if (i < NN) {
        int c    = g_cnt[i];
        int excl = g_start[i] - c + boff;
        g_start[i]  = excl;
        g_cursor[i] = excl;
        g_dinv[i]   = rsqrtf((float)(c + 1));
    }
    if (blockIdx.x == 0 && tid == 0) g_start[NN] = EE;
}

__global__ void k_fill(const void* __restrict__ ei) {
    int e = blockIdx.x * blockDim.x + threadIdx.x;
    if (e < EE) {
        int s = load_idx(ei, e);
        int t = load_idx(ei, EE + e);
        if ((unsigned)s < NN && (unsigned)t < NN) {
            int p = atomicAdd(&g_cursor[t], 1);
            g_srcCSR[p] = s;
        }
    }
}

// ---------------- GEMM (OUTC=128): 128-row tile, 256 thr, 8x8 blocking ------
// SRC: -1 = external pointer, else buffer id. DST: buffer id. blk0: chunk base.
template <int SRC, int DST>
__global__ void __launch_bounds__(256) k_gemm(const float* __restrict__ Xext,
                                              const float* __restrict__ W,
                                              const float* __restrict__ B,
                                              int blk0) {
    const float* __restrict__ X = (SRC < 0) ? Xext : buf<(SRC < 0) ? 0 : SRC>();
    float* __restrict__ OUT = buf<DST>();
    constexpr int WC = 132;
    __shared__ __align__(16) float Xs[32][WC];
    __shared__ __align__(16) float Ws[32][WC];
    int tid = threadIdx.x;
    int tx  = tid & 15;
    int ty  = tid >> 4;
    int row0 = (blk0 + blockIdx.x) * 128;

    float acc[8][8];
#pragma unroll
    for (int i = 0; i < 8; i++)
#pragma unroll
        for (int j = 0; j < 8; j++) acc[i][j] = 0.f;

    for (int k0 = 0; k0 < DH; k0 += 32) {
#pragma unroll
        for (int l = tid; l < 1024; l += 256) {
            int r  = l >> 3;
            int c4 = l & 7;
            float4 v = make_float4(0.f, 0.f, 0.f, 0.f);
            int gr = row0 + r;
            if (gr < NN) v = *(const float4*)(X + (size_t)gr * DH + k0 + c4 * 4);
            Xs[c4 * 4 + 0][r] = v.x;
            Xs[c4 * 4 + 1][r] = v.y;
            Xs[c4 * 4 + 2][r] = v.z;
            Xs[c4 * 4 + 3][r] = v.w;
        }
#pragma unroll
        for (int l = tid; l < 1024; l += 256) {
            int r = l >> 5;
            int c = (l & 31) * 4;
            float4 v = *(const float4*)(W + (size_t)(k0 + r) * DH + c);
            *(float4*)&Ws[r][c] = v;
        }
        __syncthreads();
#pragma unroll
        for (int kk = 0; kk < 32; kk++) {
            float4 x0 = *(const float4*)&Xs[kk][ty * 4];
            float4 x1 = *(const float4*)&Xs[kk][64 + ty * 4];
            float4 w0 = *(const float4*)&Ws[kk][tx * 4];
            float4 w1 = *(const float4*)&Ws[kk][64 + tx * 4];
            float xv[8] = {x0.x, x0.y, x0.z, x0.w, x1.x, x1.y, x1.z, x1.w};
            float wv[8] = {w0.x, w0.y, w0.z, w0.w, w1.x, w1.y, w1.z, w1.w};
#pragma unroll
            for (int i = 0; i < 8; i++)
#pragma unroll
                for (int j = 0; j < 8; j++) acc[i][j] += xv[i] * wv[j];
        }
        __syncthreads();
    }

    float4 B0 = *(const float4*)(B + tx * 4);
    float4 B1 = *(const float4*)(B + 64 + tx * 4);
#pragma unroll
    for (int h = 0; h < 2; h++) {
#pragma unroll
        for (int ii = 0; ii < 4; ii++) {
            int r = row0 + h * 64 + ty * 4 + ii;
            if (r >= NN) continue;
            int xi = h * 4 + ii;
            float4 o;
            o.x = acc[xi][0] + B0.x;
            o.y = acc[xi][1] + B0.y;
            o.z = acc[xi][2] + B0.z;
            o.w = acc[xi][3] + B0.w;
            *(float4*)(OUT + (size_t)r * DH + tx * 4) = o;
            o.x = acc[xi][4] + B1.x;
            o.y = acc[xi][5] + B1.y;
            o.z = acc[xi][6] + B1.z;
            o.w = acc[xi][7] + B1.w;
            *(float4*)(OUT + (size_t)r * DH + 64 + tx * 4) = o;
        }
    }
}

// ---------------- GEMM (OUTC=40): 160 thr, 8x4 blocking ---------------------
template <int SRC, int DST>
__global__ void __launch_bounds__(160) k_gemm40(const float* __restrict__ W,
                                                const float* __restrict__ B,
                                                int blk0) {
    const float* __restrict__ X = buf<SRC>();
    float* __restrict__ OUT = buf<DST>();
    __shared__ __align__(16) float Xs[32][132];
    __shared__ __align__(16) float Ws[32][44];
    int tid = threadIdx.x;
    int tx  = tid % 10;
    int ty  = tid / 10;
    int row0 = (blk0 + blockIdx.x) * 128;

    float acc[8][4];
#pragma unroll
    for (int i = 0; i < 8; i++)
#pragma unroll
        for (int j = 0; j < 4; j++) acc[i][j] = 0.f;

    for (int k0 = 0; k0 < DH; k0 += 32) {
        for (int l = tid; l < 1024; l += 160) {
            int r  = l >> 3;
            int c4 = l & 7;
            float4 v = make_float4(0.f, 0.f, 0.f, 0.f);
            int gr = row0 + r;
            if (gr < NN) v = *(const float4*)(X + (size_t)gr * DH + k0 + c4 * 4);
            Xs[c4 * 4 + 0][r] = v.x;
            Xs[c4 * 4 + 1][r] = v.y;
            Xs[c4 * 4 + 2][r] = v.z;
            Xs[c4 * 4 + 3][r] = v.w;
        }
        for (int l = tid; l < 320; l += 160) {
            int r = l / 10;
            int c = (l % 10) * 4;
            float4 v = *(const float4*)(W + (size_t)(k0 + r) * DO + c);
            *(float4*)&Ws[r][c] = v;
        }
        __syncthreads();
#pragma unroll
        for (int kk = 0; kk < 32; kk++) {
            float4 x0 = *(const float4*)&Xs[kk][ty * 8];
            float4 x1 = *(const float4*)&Xs[kk][ty * 8 + 4];
            float4 w0 = *(const float4*)&Ws[kk][tx * 4];
            float xv[8] = {x0.x, x0.y, x0.z, x0.w, x1.x, x1.y, x1.z, x1.w};
            float wv[4] = {w0.x, w0.y, w0.z, w0.w};
#pragma unroll
            for (int i = 0; i < 8; i++)
#pragma unroll
                for (int j = 0; j < 4; j++) acc[i][j] += xv[i] * wv[j];
        }
        __syncthreads();
    }

    float4 B0 = *(const float4*)(B + tx * 4);
#pragma unroll
    for (int i = 0; i < 8; i++) {
        int r = row0 + ty * 8 + i;
        if (r >= NN) continue;
        float4 o;
        o.x = acc[i][0] + B0.x;
        o.y = acc[i][1] + B0.y;
        o.z = acc[i][2] + B0.z;
        o.w = acc[i][3] + B0.w;
        *(float4*)(OUT + (size_t)r * DO + tx * 4) = o;
    }
}

// -------- aggregation (gather over CSR) + fused BN + ReLU, d=128 ------------
// one warp per node in [row0, row0+len)
template <int SRC, int DST>
__global__ void k_agg128(const float* __restrict__ gg, const float* __restrict__ be,
                         const float* __restrict__ mm, const float* __restrict__ vv,
                         int row0, int len) {
    int wl   = (blockIdx.x * blockDim.x + threadIdx.x) >> 5;
    int lane = threadIdx.x & 31;
    if (wl >= len) return;
    int w = row0 + wl;
    const float* __restrict__ h = buf<SRC>();
    float* __restrict__ OUT = buf<DST>();
    float di = g_dinv[w];
    float sn = di * di;
    float4 acc = *(const float4*)(h + (size_t)w * DH + lane * 4);
    acc.x *= sn; acc.y *= sn; acc.z *= sn; acc.w *= sn;
    int e0 = g_start[w], e1 = g_start[w + 1];
    for (int e = e0; e < e1; e++) {
        int s = g_srcCSR[e];
        float nw = g_dinv[s] * di;
        float4 v = *(const float4*)(h + (size_t)s * DH + lane * 4);
        acc.x += nw * v.x;
        acc.y += nw * v.y;
        acc.z += nw * v.z;
        acc.w += nw * v.w;
    }
    int c = lane * 4;
    float4 G  = *(const float4*)(gg + c);
    float4 BE = *(const float4*)(be + c);
    float4 M  = *(const float4*)(mm + c);
    float4 V  = *(const float4*)(vv + c);
    float r;
    r = (acc.x - M.x) * (G.x * rsqrtf(V.x + BN_EPS)) + BE.x; acc.x = fmaxf(r, 0.f);
    r = (acc.y - M.y) * (G.y * rsqrtf(V.y + BN_EPS)) + BE.y; acc.y = fmaxf(r, 0.f);
    r = (acc.z - M.z) * (G.z * rsqrtf(V.z + BN_EPS)) + BE.z; acc.z = fmaxf(r, 0.f);
    r = (acc.w - M.w) * (G.w * rsqrtf(V.w + BN_EPS)) + BE.w; acc.w = fmaxf(r, 0.f);
    *(float4*)(OUT + (size_t)w * DH + lane * 4) = acc;
}

// -------- last layer: aggregation (d=40, from g_a) + fused log_softmax ------
__global__ void k_agg40(float* __restrict__ out) {
    int w    = (blockIdx.x * blockDim.x + threadIdx.x) >> 5;
    int lane = threadIdx.x & 31;
    if (w >= NN) return;
    const float* __restrict__ h = (const float*)g_a;
    float di = g_dinv[w];
    float sn = di * di;
    const float* hr = h + (size_t)w * DO;
    float a0 = sn * hr[lane];
    float a1 = (lane < 8) ? sn * hr[32 + lane] : 0.f;
    int e0 = g_start[w], e1 = g_start[w + 1];
    for (int e = e0; e < e1; e++) {
        int s = g_srcCSR[e];
        float nw = g_dinv[s] * di;
        const float* hs = h + (size_t)s * DO;
        a0 += nw * hs[lane];
        if (lane < 8) a1 += nw * hs[32 + lane];
    }
    float mx = a0;
    if (lane < 8) mx = fmaxf(mx, a1);
#pragma unroll
    for (int off = 16; off > 0; off >>= 1)
        mx = fmaxf(mx, __shfl_xor_sync(0xffffffffu, mx, off));
    float se = expf(a0 - mx) + ((lane < 8) ? expf(a1 - mx) : 0.f);
#pragma unroll
    for (int off = 16; off > 0; off >>= 1)
        se += __shfl_xor_sync(0xffffffffu, se, off);
    float lse = mx + logf(se);
    out[(size_t)w * DO + lane] = a0 - lse;
    if (lane < 8) out[(size_t)w * DO + 32 + lane] = a1 - lse;
}

// ---------------- launch ----------------------------------------------------
extern "C" void kernel_launch(void* const* d_in, const int* in_sizes, int n_in,
                              void* d_out, int out_size) {
    const float* x  = (const float*)d_in[0];
    const void*  ei = d_in[1];
    const float* W0 = (const float*)d_in[2];
    const float* b0 = (const float*)d_in[3];
    const float* W1 = (const float*)d_in[4];
    const float* b1 = (const float*)d_in[5];
    const float* W2 = (const float*)d_in[6];
    const float* b2 = (const float*)d_in[7];
    const float* g0  = (const float*)d_in[8];
    const float* be0 = (const float*)d_in[9];
    const float* m0  = (const float*)d_in[10];
    const float* v0  = (const float*)d_in[11];
    const float* g1  = (const float*)d_in[12];
    const float* be1 = (const float*)d_in[13];
    const float* m1  = (const float*)d_in[14];
    const float* v1  = (const float*)d_in[15];
    float* out = (float*)d_out;

    const int TB = 256;
    int gbN = (NN + TB - 1) / TB;
    int gbE = (EE + TB - 1) / TB;
    int gbWarp = (NN + 7) / 8;   // warps = NN, 8 warps/block

    // streams/events: created per call, leaked (host handles only; destroying
    // mid-capture is the unsafe op).
    cudaStream_t s2;
    cudaStreamCreate(&s2);
    cudaEvent_t eFork, eCSR, eA0[NCH], eG1, eA1[NCH], eG4;
    cudaEventCreateWithFlags(&eFork, cudaEventDisableTiming);
    cudaEventCreateWithFlags(&eCSR,  cudaEventDisableTiming);
    cudaEventCreateWithFlags(&eG1,   cudaEventDisableTiming);
    cudaEventCreateWithFlags(&eG4,   cudaEventDisableTiming);
    for (int c = 0; c < NCH; c++) {
        cudaEventCreateWithFlags(&eA0[c], cudaEventDisableTiming);
        cudaEventCreateWithFlags(&eA1[c], cudaEventDisableTiming);
    }

    cudaEventRecord(eFork, 0);
    cudaStreamWaitEvent(s2, eFork, 0);

    // CSR build on side stream (hidden under gemm0)
    k_zero<<<gbN, TB, 0, s2>>>((const int*)ei);
    k_count<<<gbE, TB, 0, s2>>>(ei);
    k_scan1<<<SCAN_B, 1024, 0, s2>>>();
    k_scan23<<<gbN, TB, 0, s2>>>();
    k_fill<<<gbE, TB, 0, s2>>>(ei);
    cudaEventRecord(eCSR, s2);

    // gemm0 full on main: x -> g_h
    k_gemm<-1, 0><<<GB, TB>>>(x, W0, b0, 0);
    cudaStreamWaitEvent(0, eCSR, 0);

    // agg0 chunks on main (g_h -> g_a); gemm1 chunks trail on s2 (g_a -> g_b)
    for (int c = 0; c < NCH; c++) {
        int r0  = c * CHR;
        int len = (c == NCH - 1) ? (NN - r0) : CHR;
        k_agg128<0, 1><<<(len + 7) / 8, TB>>>(g0, be0, m0, v0, r0, len);
        cudaEventRecord(eA0[c], 0);
        cudaStreamWaitEvent(s2, eA0[c], 0);
        int nb = (c == NCH - 1) ? (GB - c * CHB) : CHB;
        k_gemm<1, 2><<<nb, TB, 0, s2>>>(nullptr, W1, b1, c * CHB);
    }
    cudaEventRecord(eG1, s2);
    cudaStreamWaitEvent(0, eG1, 0);

    // agg1 chunks on main (g_b -> g_h); gemm40 chunks trail on s2 (g_h -> g_a)
    for (int c = 0; c < NCH; c++) {
        int r0  = c * CHR;
        int len = (c == NCH - 1) ? (NN - r0) : CHR;
        k_agg128<2, 0><<<(len + 7) / 8, TB>>>(g1, be1, m1, v1, r0, len);
        cudaEventRecord(eA1[c], 0);
        cudaStreamWaitEvent(s2, eA1[c], 0);
        int nb = (c == NCH - 1) ? (GB - c * CHB) : CHB;
        k_gemm40<0, 1><<<nb, 160, 0, s2>>>(W2, b2, c * CHB);
    }
    cudaEventRecord(eG4, s2);
    cudaStreamWaitEvent(0, eG4, 0);

    // final aggregation + log_softmax: g_a -> out
    k_agg40<<<gbWarp, TB>>>(out);
}